// round 14
// baseline (speedup 1.0000x reference)
#include <cuda_runtime.h>
#include <cstdint>
#include <cstddef>

// Problem constants
#define NB   512
#define NT   2048
#define NXD  32
#define NUD  8
#define NYD  16
#define NH   128
#define ZF_DIM 44   // NXD + NUD + NTHD
#define ZH_DIM 36   // NXD + NTHD

// Scratch: h-inputs for every y output. [b][t][32]; t=0 holds x_0, t>=1 holds
// pre-clamp x_new produced by rollout step t-1. Static device array (sanctioned).
__device__ float g_xpre[(size_t)NB * NT * NXD];

// Exact XLA EmitFastTanh — bitwise-matched to the reference (verified rel_err=0).
__device__ __forceinline__ float xla_tanh(float x) {
    const float kClamp = 7.90531110763549805f;
    float ax = fabsf(x);
    float xc = fminf(fmaxf(x, -kClamp), kClamp);
    float x2 = __fmul_rn(xc, xc);
    float p;
    p = __fmaf_rn(x2, -2.76076847742355e-16f, 2.00018790482477e-13f);
    p = __fmaf_rn(x2, p, -8.60467152213735e-11f);
    p = __fmaf_rn(x2, p,  5.12229709037114e-08f);
    p = __fmaf_rn(x2, p,  1.48572235717979e-05f);
    p = __fmaf_rn(x2, p,  6.37261928875436e-04f);
    p = __fmaf_rn(x2, p,  4.89352455891786e-03f);
    p = __fmul_rn(xc, p);
    float q;
    q = __fmaf_rn(x2, 1.19825839466702e-06f, 1.18534705686654e-04f);
    q = __fmaf_rn(x2, q, 2.26843463243900e-03f);
    q = __fmaf_rn(x2, q, 4.89352518554385e-03f);
    float r = __fdiv_rn(p, q);
    return (ax < 0.0004f) ? x : r;
}

// ===================== Kernel 1: serial f-rollout =====================
// Roles (rotated across SMSPs per block): lw0 = f2 full 128-chain + state
// update; lw1 = u staging; lw2,lw3 = f1 (2 hidden units per thread).
__global__ void __launch_bounds__(128, 4)
f_rollout(const float* __restrict__ x0g, const float* __restrict__ ug,
          const float* __restrict__ thfg,
          const float* __restrict__ Wf1g, const float* __restrict__ bf1g,
          const float* __restrict__ Wf2g, const float* __restrict__ bf2g,
          const float* __restrict__ xming, const float* __restrict__ xmaxg,
          float* __restrict__ outx)
{
    __shared__ __align__(16) float WF2T[NXD * 132];   // WF2T[i*132+k] = Wf2[k][i]
    __shared__ __align__(16) float hf[NH];
    __shared__ __align__(16) float zf0[48], zf1[48];  // [x(32)|u(8)|thf(4)|pad]

    const int tt   = threadIdx.x;
    const int w    = tt >> 5;
    const int lane = tt & 31;
    const int b    = blockIdx.x;

    // SMSP role rotation (proven win in r11).
    const int rot = (b >> 2) & 3;
    const int lw  = (w + 4 - rot) & 3;

    const float* ub  = ug   + (size_t)b * NT * NUD;
    float*       oxb = outx + (size_t)b * NT * NXD;
    float*       xpb = g_xpre + (size_t)b * NT * NXD;

    // ---- f1 weights in registers (lw2: units lane/lane+64; lw3: 32+lane/96+lane) ----
    float wA[ZF_DIM], wB[ZF_DIM];
    float bA = 0.f, bB = 0.f, bf2v = 0.f, xlo = 0.f, xhi = 0.f;
    int u0 = 0;
    if (lw >= 2) {
        u0 = (lw == 2) ? lane : 32 + lane;
#pragma unroll
        for (int k = 0; k < ZF_DIM; k++) {
            wA[k] = Wf1g[k * NH + u0];
            wB[k] = Wf1g[k * NH + u0 + 64];
        }
        bA = bf1g[u0];
        bB = bf1g[u0 + 64];
    } else if (lw == 0) {
        bf2v = bf2g[lane];
        xlo = xming[0]; xhi = xmaxg[0];
    }

    // ---- stage transposed f2 weights (conflict-free .128 rows) ----
    for (int e = tt; e < NH * NXD; e += 128) {
        int k = e >> 5, i = e & 31;
        WF2T[i * 132 + k] = Wf2g[e];
    }

    // ---- state init ----
    if (tt < 32) {
        float xv = x0g[b * 32 + tt];
        zf0[tt] = xv;
        oxb[tt] = xv;            // x output index 0 is x_0
        xpb[tt] = xv;            // h input for y[0] is x_0
    }
    if (tt >= 32 && tt < 40) zf0[tt] = ub[tt - 32];            // u_0
    if (tt >= 40 && tt < 44) {
        float th = thfg[b * 4 + (tt - 40)];
        zf0[tt] = th; zf1[tt] = th;                            // theta_f both bufs
    }
    __syncthreads();

    // ---- one step, parity statically resolved ----
    auto step = [&](int t, const float* zfc, float* zfn) {
        if (lw >= 2) {
            // f1: two strict ascending-k 44-chains (reg weights, broadcast z)
            float a0 = 0.f, a1 = 0.f;
#pragma unroll
            for (int q = 0; q < ZF_DIM / 4; q++) {
                float4 z4 = *(const float4*)(zfc + 4 * q);
                a0 = __fmaf_rn(z4.x, wA[4 * q + 0], a0);
                a1 = __fmaf_rn(z4.x, wB[4 * q + 0], a1);
                a0 = __fmaf_rn(z4.y, wA[4 * q + 1], a0);
                a1 = __fmaf_rn(z4.y, wB[4 * q + 1], a1);
                a0 = __fmaf_rn(z4.z, wA[4 * q + 2], a0);
                a1 = __fmaf_rn(z4.z, wB[4 * q + 2], a1);
                a0 = __fmaf_rn(z4.w, wA[4 * q + 3], a0);
                a1 = __fmaf_rn(z4.w, wB[4 * q + 3], a1);
            }
            hf[u0]      = xla_tanh(__fadd_rn(a0, bA));
            hf[u0 + 64] = xla_tanh(__fadd_rn(a1, bB));
        } else if (lw == 1) {
            // u staging for step t+1 (off the critical path)
            float ureg = 0.f;
            if (lane < 8) ureg = ub[(size_t)(t + 1) * NUD + lane];
            if (lane == 8 && t + 8 < NT)
                asm volatile("prefetch.global.L2 [%0];" :: "l"(ub + (size_t)(t + 8) * NUD));
            if (lane < 8) zfn[32 + lane] = ureg;
        }
        __syncthreads();                       // hf ready

        if (lw == 0) {
            // f2: strict 128-chain, smem weights; loads pipeline ahead of chain
            float acc = 0.f;
            const float* wr = WF2T + lane * 132;
#pragma unroll
            for (int q = 0; q < NH / 4; q++) {
                float4 h4 = *(const float4*)(hf + 4 * q);
                float4 w4 = *(const float4*)(wr + 4 * q);
                acc = __fmaf_rn(h4.x, w4.x, acc);
                acc = __fmaf_rn(h4.y, w4.y, acc);
                acc = __fmaf_rn(h4.z, w4.z, acc);
                acc = __fmaf_rn(h4.w, w4.w, acc);
            }
            float dx = __fadd_rn(acc, bf2v);
            float xn = __fadd_rn(zfc[lane], dx);     // pre-clamp x_new
            xpb[(size_t)(t + 1) * NXD + lane] = xn;  // h input for y[t+1]
            float xc = fminf(fmaxf(xn, xlo), xhi);
            zfn[lane] = xc;                          // clamped carry
            oxb[(size_t)(t + 1) * NXD + lane] = xc;
        }
        __syncthreads();                       // zfn ready
    };

    for (int t = 0; t < NT - 2; t += 2) {
        step(t,     zf0, zf1);
        step(t + 1, zf1, zf0);
    }
    step(NT - 2, zf0, zf1);    // t = 2046 (even)
}

// ===================== Kernel 2: batch h evaluation =====================
// y[b][t] = h(g_xpre[b][t]); clamp for t>0; y[b][0] unclamped.
// 4096 blocks = 512 b x 8 stripes of 256 t; tiles of 4 rows.
// Phase 2 is a 2-segment ordered chain across all 128 threads with weights
// in registers (thread (seg, r, i) owns Wh2[seg*64 .. seg*64+63][i]).
__global__ void __launch_bounds__(128, 4)
h_eval(const float* __restrict__ thhg,
       const float* __restrict__ Wh1g, const float* __restrict__ bh1g,
       const float* __restrict__ Wh2g, const float* __restrict__ bh2g,
       const float* __restrict__ yming, const float* __restrict__ ymaxg,
       float* __restrict__ outy)
{
    __shared__ __align__(16) float zsm[4 * 40];       // 4 rows x [x(32)|thh(4)|pad]
    __shared__ __align__(16) float hhs[4 * NH];
    __shared__ __align__(16) float psm[64];           // phase-2 segment partials

    const int tt = threadIdx.x;
    const int b      = blockIdx.x >> 3;
    const int stripe = blockIdx.x & 7;
    const int t0base = stripe * (NT / 8);   // 256 t's per stripe

    const int i   = tt & 15;          // phase-2 output
    const int r   = (tt >> 4) & 3;    // phase-2 row
    const int seg = tt >> 6;          // phase-2 k-segment (0: k<64, 1: k>=64)

    // h1 weights: one unit per thread, registers
    float wh1[ZH_DIM];
#pragma unroll
    for (int k = 0; k < ZH_DIM; k++) wh1[k] = Wh1g[k * NH + tt];
    const float bh1v = bh1g[tt];

    // h2 segment weights: 64 registers per thread
    float w2s[64];
#pragma unroll
    for (int k = 0; k < 64; k++) w2s[k] = Wh2g[(seg * 64 + k) * NYD + i];
    const float bh2v = bh2g[i];
    const float ylo = yming[0], yhi = ymaxg[0];

    if (tt < 16) {                       // theta_h + zero pad, persistent slots
        int rr = tt >> 2, j = tt & 3;
        zsm[rr * 40 + 32 + j] = thhg[b * 4 + j];
        zsm[rr * 40 + 36 + j] = 0.f;
    }
    __syncthreads();

    const float* xp  = g_xpre + (size_t)b * NT * NXD;
    float*       oyb = outy   + (size_t)b * NT * NYD;

    for (int tile = 0; tile < 64; tile++) {
        const int t0 = t0base + tile * 4;
        // load 4 rows of x (contiguous 512B, fully coalesced)
        {
            int rr = tt >> 5, k = tt & 31;
            zsm[rr * 40 + k] = xp[(size_t)(t0 + rr) * NXD + k];
        }
        __syncthreads();

        // phase 1: h1 unit tt for 4 rows (4 independent ascending 36-chains)
        float a0 = 0.f, a1 = 0.f, a2 = 0.f, a3 = 0.f;
#pragma unroll
        for (int q = 0; q < ZH_DIM / 4; q++) {
            float4 z0 = *(const float4*)(zsm + 0 * 40 + 4 * q);
            float4 z1 = *(const float4*)(zsm + 1 * 40 + 4 * q);
            float4 z2 = *(const float4*)(zsm + 2 * 40 + 4 * q);
            float4 z3 = *(const float4*)(zsm + 3 * 40 + 4 * q);
            a0 = __fmaf_rn(z0.x, wh1[4 * q + 0], a0);
            a1 = __fmaf_rn(z1.x, wh1[4 * q + 0], a1);
            a2 = __fmaf_rn(z2.x, wh1[4 * q + 0], a2);
            a3 = __fmaf_rn(z3.x, wh1[4 * q + 0], a3);
            a0 = __fmaf_rn(z0.y, wh1[4 * q + 1], a0);
            a1 = __fmaf_rn(z1.y, wh1[4 * q + 1], a1);
            a2 = __fmaf_rn(z2.y, wh1[4 * q + 1], a2);
            a3 = __fmaf_rn(z3.y, wh1[4 * q + 1], a3);
            a0 = __fmaf_rn(z0.z, wh1[4 * q + 2], a0);
            a1 = __fmaf_rn(z1.z, wh1[4 * q + 2], a1);
            a2 = __fmaf_rn(z2.z, wh1[4 * q + 2], a2);
            a3 = __fmaf_rn(z3.z, wh1[4 * q + 2], a3);
            a0 = __fmaf_rn(z0.w, wh1[4 * q + 3], a0);
            a1 = __fmaf_rn(z1.w, wh1[4 * q + 3], a1);
            a2 = __fmaf_rn(z2.w, wh1[4 * q + 3], a2);
            a3 = __fmaf_rn(z3.w, wh1[4 * q + 3], a3);
        }
        hhs[0 * NH + tt] = xla_tanh(__fadd_rn(a0, bh1v));
        hhs[1 * NH + tt] = xla_tanh(__fadd_rn(a1, bh1v));
        hhs[2 * NH + tt] = xla_tanh(__fadd_rn(a2, bh1v));
        hhs[3 * NH + tt] = xla_tanh(__fadd_rn(a3, bh1v));
        __syncthreads();

        // phase 2 segment A: k = 0..63, single accumulator, reg weights
        if (seg == 0) {
            const float* hh = hhs + r * NH;
            float acc = 0.f;
#pragma unroll
            for (int q = 0; q < 16; q++) {
                float4 h4 = *(const float4*)(hh + 4 * q);
                acc = __fmaf_rn(h4.x, w2s[4 * q + 0], acc);
                acc = __fmaf_rn(h4.y, w2s[4 * q + 1], acc);
                acc = __fmaf_rn(h4.z, w2s[4 * q + 2], acc);
                acc = __fmaf_rn(h4.w, w2s[4 * q + 3], acc);
            }
            psm[tt] = acc;     // tt == r*16+i for seg 0
        }
        __syncthreads();

        // phase 2 segment B: continue the SAME accumulator, k = 64..127
        if (seg == 1) {
            const float* hh = hhs + r * NH + 64;
            float acc = psm[tt - 64];
#pragma unroll
            for (int q = 0; q < 16; q++) {
                float4 h4 = *(const float4*)(hh + 4 * q);
                acc = __fmaf_rn(h4.x, w2s[4 * q + 0], acc);
                acc = __fmaf_rn(h4.y, w2s[4 * q + 1], acc);
                acc = __fmaf_rn(h4.z, w2s[4 * q + 2], acc);
                acc = __fmaf_rn(h4.w, w2s[4 * q + 3], acc);
            }
            float y = __fadd_rn(acc, bh2v);
            const int gt = t0 + r;
            if (gt > 0) y = fminf(fmaxf(y, ylo), yhi);   // y[0] unclamped
            oyb[(size_t)gt * NYD + i] = y;
        }
        __syncthreads();
    }
}

extern "C" void kernel_launch(void* const* d_in, const int* in_sizes, int n_in,
                              void* d_out, int out_size) {
    (void)in_sizes; (void)n_in; (void)out_size;

    const float* x0   = (const float*)d_in[0];
    const float* u    = (const float*)d_in[1];
    const float* thf  = (const float*)d_in[2];
    const float* thh  = (const float*)d_in[3];
    const float* Wf1  = (const float*)d_in[4];
    const float* bf1  = (const float*)d_in[5];
    const float* Wf2  = (const float*)d_in[6];
    const float* bf2  = (const float*)d_in[7];
    const float* Wh1  = (const float*)d_in[8];
    const float* bh1  = (const float*)d_in[9];
    const float* Wh2  = (const float*)d_in[10];
    const float* bh2  = (const float*)d_in[11];
    const float* xmin = (const float*)d_in[12];
    const float* xmax = (const float*)d_in[13];
    const float* ymin = (const float*)d_in[14];
    const float* ymax = (const float*)d_in[15];

    float* outx = (float*)d_out;
    float* outy = outx + (size_t)NB * NT * NXD;

    f_rollout<<<NB, 128>>>(x0, u, thf, Wf1, bf1, Wf2, bf2, xmin, xmax, outx);
    h_eval<<<NB * 8, 128>>>(thh, Wh1, bh1, Wh2, bh2, ymin, ymax, outy);
}

// round 15
// speedup vs baseline: 1.2409x; 1.2409x over previous
#include <cuda_runtime.h>
#include <cstdint>
#include <cstddef>

// Problem constants
#define NB   512
#define NT   2048
#define NXD  32
#define NUD  8
#define NYD  16
#define NH   128
#define ZF_DIM 44   // NXD + NUD + NTHD
#define ZH_DIM 36   // NXD + NTHD

// Scratch: h-inputs for every y output. [b][t][32]; t=0 holds x_0, t>=1 holds
// pre-clamp x_new produced by rollout step t-1. Static device array (sanctioned).
__device__ float g_xpre[(size_t)NB * NT * NXD];

// Exact XLA EmitFastTanh — bitwise-matched to the reference (verified rel_err=0).
__device__ __forceinline__ float xla_tanh(float x) {
    const float kClamp = 7.90531110763549805f;
    float ax = fabsf(x);
    float xc = fminf(fmaxf(x, -kClamp), kClamp);
    float x2 = __fmul_rn(xc, xc);
    float p;
    p = __fmaf_rn(x2, -2.76076847742355e-16f, 2.00018790482477e-13f);
    p = __fmaf_rn(x2, p, -8.60467152213735e-11f);
    p = __fmaf_rn(x2, p,  5.12229709037114e-08f);
    p = __fmaf_rn(x2, p,  1.48572235717979e-05f);
    p = __fmaf_rn(x2, p,  6.37261928875436e-04f);
    p = __fmaf_rn(x2, p,  4.89352455891786e-03f);
    p = __fmul_rn(xc, p);
    float q;
    q = __fmaf_rn(x2, 1.19825839466702e-06f, 1.18534705686654e-04f);
    q = __fmaf_rn(x2, q, 2.26843463243900e-03f);
    q = __fmaf_rn(x2, q, 4.89352518554385e-03f);
    float r = __fdiv_rn(p, q);
    return (ax < 0.0004f) ? x : r;
}

// f2 segment weights live in the SAME register arrays as f1 weights (role
// union — avoids live-range double counting). k is always a compile-time
// constant here so the ternary folds to a direct register reference.
#define WS(k) ((k) < 44 ? wA[(k)] : wB[(k) - 44])

#define BAR_SEG() asm volatile("bar.sync 1, 64;" ::: "memory")  // lw0 + lw1

// ===================== Kernel 1: serial f-rollout (r12 winner, verbatim) =====
__global__ void __launch_bounds__(128, 4)
f_rollout(const float* __restrict__ x0g, const float* __restrict__ ug,
          const float* __restrict__ thfg,
          const float* __restrict__ Wf1g, const float* __restrict__ bf1g,
          const float* __restrict__ Wf2g, const float* __restrict__ bf2g,
          const float* __restrict__ xming, const float* __restrict__ xmaxg,
          float* __restrict__ outx)
{
    __shared__ __align__(16) float hf[NH];
    __shared__ __align__(16) float partial[32];
    __shared__ __align__(16) float zf0[48], zf1[48];  // [x(32)|u(8)|thf(4)|pad]

    const int tt   = threadIdx.x;
    const int w    = tt >> 5;
    const int lane = tt & 31;
    const int b    = blockIdx.x;

    // SMSP role rotation (proven win in r11).
    const int rot = (b >> 2) & 3;
    const int lw  = (w + 4 - rot) & 3;

    const float* ub  = ug   + (size_t)b * NT * NUD;
    float*       oxb = outx + (size_t)b * NT * NXD;
    float*       xpb = g_xpre + (size_t)b * NT * NXD;

    // ---- register weights by role ----
    // lw2: f1 units (lane, lane+64).  lw3: f1 units (32+lane, 96+lane).
    // lw0: f2 seg A (k=0..63).        lw1: f2 seg B (k=64..127).
    float wA[44], wB[44];
    float bA = 0.f, bB = 0.f, bf2v = 0.f, xlo = 0.f, xhi = 0.f;
    int u0 = 0;
    if (lw >= 2) {
        u0 = (lw == 2) ? lane : 32 + lane;
#pragma unroll
        for (int k = 0; k < ZF_DIM; k++) {
            wA[k] = Wf1g[k * NH + u0];
            wB[k] = Wf1g[k * NH + u0 + 64];
        }
        bA = bf1g[u0];
        bB = bf1g[u0 + 64];
    } else if (lw == 0) {
#pragma unroll
        for (int k = 0; k < 64; k++) WS(k) = Wf2g[k * NXD + lane];
    } else {
#pragma unroll
        for (int k = 0; k < 64; k++) WS(k) = Wf2g[(64 + k) * NXD + lane];
        bf2v = bf2g[lane];
        xlo = xming[0]; xhi = xmaxg[0];
    }

    // ---- state init ----
    if (tt < 32) {
        float xv = x0g[b * 32 + tt];
        zf0[tt] = xv;
        oxb[tt] = xv;            // x output index 0 is x_0
        xpb[tt] = xv;            // h input for y[0] is x_0
    }
    if (tt >= 32 && tt < 40) zf0[tt] = ub[tt - 32];            // u_0
    if (tt >= 40 && tt < 44) {
        float th = thfg[b * 4 + (tt - 40)];
        zf0[tt] = th; zf1[tt] = th;                            // theta_f both bufs
    }
    __syncthreads();

    // ---- one step, parity statically resolved ----
    auto step = [&](int t, const float* zfc, float* zfn) {
        float ureg = 0.f;
        if (lw >= 2) {
            // f1: two strict ascending-k 44-chains (reg weights, broadcast z)
            float a0 = 0.f, a1 = 0.f;
#pragma unroll
            for (int q = 0; q < ZF_DIM / 4; q++) {
                float4 z4 = *(const float4*)(zfc + 4 * q);
                a0 = __fmaf_rn(z4.x, wA[4 * q + 0], a0);
                a1 = __fmaf_rn(z4.x, wB[4 * q + 0], a1);
                a0 = __fmaf_rn(z4.y, wA[4 * q + 1], a0);
                a1 = __fmaf_rn(z4.y, wB[4 * q + 1], a1);
                a0 = __fmaf_rn(z4.z, wA[4 * q + 2], a0);
                a1 = __fmaf_rn(z4.z, wB[4 * q + 2], a1);
                a0 = __fmaf_rn(z4.w, wA[4 * q + 3], a0);
                a1 = __fmaf_rn(z4.w, wB[4 * q + 3], a1);
            }
            hf[u0]      = xla_tanh(__fadd_rn(a0, bA));
            hf[u0 + 64] = xla_tanh(__fadd_rn(a1, bB));
        } else if (lw == 0) {
            if (lane < 8) ureg = ub[(size_t)(t + 1) * NUD + lane];
            if (lane == 8 && t + 8 < NT)
                asm volatile("prefetch.global.L2 [%0];" :: "l"(ub + (size_t)(t + 8) * NUD));
        }
        __syncthreads();                       // hf ready

        if (lw == 0) {
            // f2 segment A: ordered k = 0..63, reg weights, broadcast hf
            float acc = 0.f;
#pragma unroll
            for (int q = 0; q < 16; q++) {
                float4 h4 = *(const float4*)(hf + 4 * q);
                acc = __fmaf_rn(h4.x, WS(4 * q + 0), acc);
                acc = __fmaf_rn(h4.y, WS(4 * q + 1), acc);
                acc = __fmaf_rn(h4.z, WS(4 * q + 2), acc);
                acc = __fmaf_rn(h4.w, WS(4 * q + 3), acc);
            }
            partial[lane] = acc;
            BAR_SEG();
            if (lane < 8) zfn[32 + lane] = ureg;     // stage u_{t+1}
        } else if (lw == 1) {
            BAR_SEG();
            // f2 segment B: continue the SAME accumulator, k = 64..127
            float acc = partial[lane];
#pragma unroll
            for (int q = 0; q < 16; q++) {
                float4 h4 = *(const float4*)(hf + 64 + 4 * q);
                acc = __fmaf_rn(h4.x, WS(4 * q + 0), acc);
                acc = __fmaf_rn(h4.y, WS(4 * q + 1), acc);
                acc = __fmaf_rn(h4.z, WS(4 * q + 2), acc);
                acc = __fmaf_rn(h4.w, WS(4 * q + 3), acc);
            }
            float dx = __fadd_rn(acc, bf2v);
            float xn = __fadd_rn(zfc[lane], dx);     // pre-clamp x_new
            xpb[(size_t)(t + 1) * NXD + lane] = xn;  // h input for y[t+1]
            float xc = fminf(fmaxf(xn, xlo), xhi);
            zfn[lane] = xc;                          // clamped carry
            oxb[(size_t)(t + 1) * NXD + lane] = xc;
        }
        __syncthreads();
    };

    for (int t = 0; t < NT - 2; t += 2) {
        step(t,     zf0, zf1);
        step(t + 1, zf1, zf0);
    }
    step(NT - 2, zf0, zf1);    // t = 2046 (even)
}

// ===================== Kernel 2: batch h evaluation (v2: weight reuse) ======
// y[b][t] = h(g_xpre[b][t]); clamp for t>0; y[b][0] unclamped.
// 4096 blocks = 512 b x 8 stripes of 256 t; tiles of 16 rows.
// Phase 2: thread (i, rowgroup) sweeps k once, loads each w4 ONCE and updates
// 4 row-accumulators — each a strict ascending-k single-accumulator chain.
__global__ void __launch_bounds__(128, 5)
h_eval(const float* __restrict__ thhg,
       const float* __restrict__ Wh1g, const float* __restrict__ bh1g,
       const float* __restrict__ Wh2g, const float* __restrict__ bh2g,
       const float* __restrict__ yming, const float* __restrict__ ymaxg,
       float* __restrict__ outy)
{
    __shared__ __align__(16) float WH2T[NYD * 132];   // WH2T[i*132+k] = Wh2[k][i]
    __shared__ __align__(16) float zsm[16 * 40];      // 16 rows x [x(32)|thh(4)|pad]
    __shared__ __align__(16) float hhs[16 * NH];      // 8 KB

    const int tt = threadIdx.x;
    const int b      = blockIdx.x >> 3;
    const int stripe = blockIdx.x & 7;
    const int t0base = stripe * (NT / 8);   // 256 t's per stripe

    // h1 weights: one unit per thread, registers
    float wh1[ZH_DIM];
#pragma unroll
    for (int k = 0; k < ZH_DIM; k++) wh1[k] = Wh1g[k * NH + tt];
    const float bh1v = bh1g[tt];
    const float bh2v = bh2g[tt & 15];
    const float ylo = yming[0], yhi = ymaxg[0];

    // stage transposed h2 weights (conflict-light .128 rows)
    for (int e = tt; e < NH * NYD; e += 128) {
        int k = e >> 4, i = e & 15;
        WH2T[i * 132 + k] = Wh2g[e];
    }
    if (tt < 64) {                       // theta_h + zero pad, persistent slots
        int rr = tt >> 2, j = tt & 3;
        zsm[rr * 40 + 32 + j] = thhg[b * 4 + j];
        zsm[rr * 40 + 36 + j] = 0.f;
    }
    __syncthreads();

    const float* xp  = g_xpre + (size_t)b * NT * NXD;
    float*       oyb = outy   + (size_t)b * NT * NYD;

    for (int tile = 0; tile < 16; tile++) {
        const int t0 = t0base + tile * 16;
        // load 16 rows of x (2 KB, coalesced)
#pragma unroll
        for (int idx = tt; idx < 512; idx += 128) {
            int rr = idx >> 5, k = idx & 31;
            zsm[rr * 40 + k] = xp[(size_t)(t0 + rr) * NXD + k];
        }
        __syncthreads();

        // phase 1: h1 unit tt for 16 rows, in 4 groups of 4 (ascending 36-chains)
#pragma unroll
        for (int g = 0; g < 4; g++) {
            const float* zg = zsm + g * 160;
            float a0 = 0.f, a1 = 0.f, a2 = 0.f, a3 = 0.f;
#pragma unroll
            for (int q = 0; q < ZH_DIM / 4; q++) {
                float4 z0 = *(const float4*)(zg + 0 * 40 + 4 * q);
                float4 z1 = *(const float4*)(zg + 1 * 40 + 4 * q);
                float4 z2 = *(const float4*)(zg + 2 * 40 + 4 * q);
                float4 z3 = *(const float4*)(zg + 3 * 40 + 4 * q);
                a0 = __fmaf_rn(z0.x, wh1[4 * q + 0], a0);
                a1 = __fmaf_rn(z1.x, wh1[4 * q + 0], a1);
                a2 = __fmaf_rn(z2.x, wh1[4 * q + 0], a2);
                a3 = __fmaf_rn(z3.x, wh1[4 * q + 0], a3);
                a0 = __fmaf_rn(z0.y, wh1[4 * q + 1], a0);
                a1 = __fmaf_rn(z1.y, wh1[4 * q + 1], a1);
                a2 = __fmaf_rn(z2.y, wh1[4 * q + 1], a2);
                a3 = __fmaf_rn(z3.y, wh1[4 * q + 1], a3);
                a0 = __fmaf_rn(z0.z, wh1[4 * q + 2], a0);
                a1 = __fmaf_rn(z1.z, wh1[4 * q + 2], a1);
                a2 = __fmaf_rn(z2.z, wh1[4 * q + 2], a2);
                a3 = __fmaf_rn(z3.z, wh1[4 * q + 2], a3);
                a0 = __fmaf_rn(z0.w, wh1[4 * q + 3], a0);
                a1 = __fmaf_rn(z1.w, wh1[4 * q + 3], a1);
                a2 = __fmaf_rn(z2.w, wh1[4 * q + 3], a2);
                a3 = __fmaf_rn(z3.w, wh1[4 * q + 3], a3);
            }
            hhs[(g * 4 + 0) * NH + tt] = xla_tanh(__fadd_rn(a0, bh1v));
            hhs[(g * 4 + 1) * NH + tt] = xla_tanh(__fadd_rn(a1, bh1v));
            hhs[(g * 4 + 2) * NH + tt] = xla_tanh(__fadd_rn(a2, bh1v));
            hhs[(g * 4 + 3) * NH + tt] = xla_tanh(__fadd_rn(a3, bh1v));
        }
        __syncthreads();

        // phase 2: thread (i = tt&15, rg = tt>>4 in 0..3) computes output i for
        // rows rg*4..rg*4+3. One k-sweep; each w4 loaded once, 4 accumulators,
        // each a strict ascending-k chain.
        if (tt < 64) {
            const int i  = tt & 15;
            const int rg = tt >> 4;
            const float* wr = WH2T + i * 132;
            const float* h0 = hhs + (rg * 4 + 0) * NH;
            const float* h1 = hhs + (rg * 4 + 1) * NH;
            const float* h2 = hhs + (rg * 4 + 2) * NH;
            const float* h3 = hhs + (rg * 4 + 3) * NH;
            float c0 = 0.f, c1 = 0.f, c2 = 0.f, c3 = 0.f;
#pragma unroll
            for (int q = 0; q < NH / 4; q++) {
                float4 w4 = *(const float4*)(wr + 4 * q);
                float4 a4 = *(const float4*)(h0 + 4 * q);
                float4 b4 = *(const float4*)(h1 + 4 * q);
                float4 d4 = *(const float4*)(h2 + 4 * q);
                float4 e4 = *(const float4*)(h3 + 4 * q);
                c0 = __fmaf_rn(a4.x, w4.x, c0);
                c1 = __fmaf_rn(b4.x, w4.x, c1);
                c2 = __fmaf_rn(d4.x, w4.x, c2);
                c3 = __fmaf_rn(e4.x, w4.x, c3);
                c0 = __fmaf_rn(a4.y, w4.y, c0);
                c1 = __fmaf_rn(b4.y, w4.y, c1);
                c2 = __fmaf_rn(d4.y, w4.y, c2);
                c3 = __fmaf_rn(e4.y, w4.y, c3);
                c0 = __fmaf_rn(a4.z, w4.z, c0);
                c1 = __fmaf_rn(b4.z, w4.z, c1);
                c2 = __fmaf_rn(d4.z, w4.z, c2);
                c3 = __fmaf_rn(e4.z, w4.z, c3);
                c0 = __fmaf_rn(a4.w, w4.w, c0);
                c1 = __fmaf_rn(b4.w, w4.w, c1);
                c2 = __fmaf_rn(d4.w, w4.w, c2);
                c3 = __fmaf_rn(e4.w, w4.w, c3);
            }
            float y0 = __fadd_rn(c0, bh2v);
            float y1 = __fadd_rn(c1, bh2v);
            float y2 = __fadd_rn(c2, bh2v);
            float y3 = __fadd_rn(c3, bh2v);
            const int gt = t0 + rg * 4;
            if (gt > 0) y0 = fminf(fmaxf(y0, ylo), yhi);   // y[0] unclamped
            y1 = fminf(fmaxf(y1, ylo), yhi);
            y2 = fminf(fmaxf(y2, ylo), yhi);
            y3 = fminf(fmaxf(y3, ylo), yhi);
            oyb[(size_t)(gt + 0) * NYD + i] = y0;
            oyb[(size_t)(gt + 1) * NYD + i] = y1;
            oyb[(size_t)(gt + 2) * NYD + i] = y2;
            oyb[(size_t)(gt + 3) * NYD + i] = y3;
        }
        __syncthreads();
    }
}

extern "C" void kernel_launch(void* const* d_in, const int* in_sizes, int n_in,
                              void* d_out, int out_size) {
    (void)in_sizes; (void)n_in; (void)out_size;

    const float* x0   = (const float*)d_in[0];
    const float* u    = (const float*)d_in[1];
    const float* thf  = (const float*)d_in[2];
    const float* thh  = (const float*)d_in[3];
    const float* Wf1  = (const float*)d_in[4];
    const float* bf1  = (const float*)d_in[5];
    const float* Wf2  = (const float*)d_in[6];
    const float* bf2  = (const float*)d_in[7];
    const float* Wh1  = (const float*)d_in[8];
    const float* bh1  = (const float*)d_in[9];
    const float* Wh2  = (const float*)d_in[10];
    const float* bh2  = (const float*)d_in[11];
    const float* xmin = (const float*)d_in[12];
    const float* xmax = (const float*)d_in[13];
    const float* ymin = (const float*)d_in[14];
    const float* ymax = (const float*)d_in[15];

    float* outx = (float*)d_out;
    float* outy = outx + (size_t)NB * NT * NXD;

    f_rollout<<<NB, 128>>>(x0, u, thf, Wf1, bf1, Wf2, bf2, xmin, xmax, outx);
    h_eval<<<NB * 8, 128>>>(thh, Wh1, bh1, Wh2, bh2, ymin, ymax, outy);
}